// round 1
// baseline (speedup 1.0000x reference)
#include <cuda_runtime.h>
#include <math.h>

// Problem constants
#define C_      32
#define KK_     9          // K*K
#define OH_     64
#define OW_     64
#define B_      8
#define INCH    201        // K*C*2 + K*K
#define KP      204        // padded K (multiple of 4)
#define OUTCH   1152       // C*NEW*NEW*K*K
#define PTILE   64         // pixels per block (8x8 spatial tile)
#define NKQ     (KP/4)     // 51 k-quads

#define SMEM_FLOATS (C_*KK_*PTILE + NKQ*256)
#define SMEM_BYTES  (SMEM_FLOATS * 4)

// Scratch: BN-folded, k-padded weight matrix + bias (static __device__, no allocs)
__device__ float g_wpack[OUTCH * KP];
__device__ float g_bias[OUTCH];

// ---------------------------------------------------------------------------
// Repack: fold BN scale into conv_w rows, pad K 201 -> 204 with zeros.
// y = relu(dot(feat, w*scale) + (beta - mean*scale))
// ---------------------------------------------------------------------------
__global__ void repack_kernel(const float* __restrict__ w,
                              const float* __restrict__ gamma,
                              const float* __restrict__ beta,
                              const float* __restrict__ mean,
                              const float* __restrict__ var) {
    int m = blockIdx.x;
    float sc = gamma[m] / sqrtf(var[m] + 1e-5f);
    if (threadIdx.x == 0) g_bias[m] = beta[m] - mean[m] * sc;
    for (int k = threadIdx.x; k < KP; k += blockDim.x)
        g_wpack[m * KP + k] = (k < INCH) ? w[m * INCH + k] * sc : 0.f;
}

// Packed fp32x2 FMA (Blackwell): both halves carry different K elements, so
// accumulator = (even-k partial, odd-k partial). No operand duplication needed.
__device__ __forceinline__ void fma2(unsigned long long& acc,
                                     unsigned long long a, unsigned long long b) {
    asm("fma.rn.f32x2 %0, %1, %2, %0;" : "+l"(acc) : "l"(a), "l"(b));
}
__device__ __forceinline__ float2 u2f(unsigned long long v) {
    float2 r; asm("mov.b64 {%0, %1}, %2;" : "=f"(r.x), "=f"(r.y) : "l"(v)); return r;
}
// XOR swizzle of the 16B-chunk index so that 8 threads reading stride-64B are
// bank-conflict-free on LDS.128 (otherwise 4-way conflict -> LDS-bound).
__device__ __forceinline__ int swz(int p) { return p ^ ((p >> 3) & 7); }

// ---------------------------------------------------------------------------
// Fused main kernel. Block = one batch x 8x8 output-pixel tile (64 pixels).
// Phase 1: gather 3x3 stride-2 patches into SMEM [c][kk][p]
// Phase 2: feat[201] per pixel = concat(max_c, max_i, max_j) into swizzled SMEM
// Phase 3: per-thread (c,u,v) x 4-pixel register tile: 9 dot products of
//          length 204 via f32x2 FMA; fused BN+ReLU+patch-weighted mean; store.
// ---------------------------------------------------------------------------
__global__ __launch_bounds__(256, 1)
void revo_main(const float* __restrict__ x, float* __restrict__ out) {
    extern __shared__ float sm[];
    float* patch_s = sm;                      // [32][9][64]
    float* feat_s  = sm + C_ * KK_ * PTILE;   // [51 kq][64 swz 16B-chunks][4]

    const int b   = blockIdx.z;
    const int oy0 = blockIdx.y * 8;
    const int ox0 = blockIdx.x * 8;
    const int tid = threadIdx.x;
    const float* xb = x + (size_t)b * C_ * 128 * 128;

    // ---- Phase 1: patches ----
    for (int e = tid; e < C_ * KK_ * PTILE; e += 256) {
        int p  = e & 63;
        int kk = (e >> 6) % 9;
        int c  = e / (KK_ * PTILE);
        int oyl = p >> 3, oxl = p & 7;
        int ki = kk / 3, kj = kk - ki * 3;
        int iy = 2 * (oy0 + oyl) - 1 + ki;
        int ix = 2 * (ox0 + oxl) - 1 + kj;
        float v = 0.f;
        if ((unsigned)iy < 128u && (unsigned)ix < 128u)
            v = xb[c * 16384 + iy * 128 + ix];
        patch_s[e] = v;   // e == (c*9+kk)*64 + p
    }
    __syncthreads();

    // ---- Phase 2: feat ----
    const float NEGINF = -3.402823466e38f;
    for (int e = tid; e < KP * PTILE; e += 256) {   // exactly 51 iters
        int p = e & 63;
        int k = e >> 6;
        float v;
        if (k < 9) {                                  // max over channels
            v = NEGINF;
            #pragma unroll
            for (int c = 0; c < C_; ++c)
                v = fmaxf(v, patch_s[(c * KK_ + k) * PTILE + p]);
        } else if (k < 9 + 96) {                      // max over kernel rows i
            int t = k - 9; int c = t / 3, j = t - (t / 3) * 3;
            const float* pb = &patch_s[(c * KK_ + j) * PTILE + p];
            v = fmaxf(fmaxf(pb[0], pb[3 * PTILE]), pb[6 * PTILE]);
        } else if (k < INCH) {                        // max over kernel cols j
            int t = k - 105; int c = t / 3, i = t - (t / 3) * 3;
            const float* pb = &patch_s[(c * KK_ + i * 3) * PTILE + p];
            v = fmaxf(fmaxf(pb[0], pb[PTILE]), pb[2 * PTILE]);
        } else {
            v = 0.f;                                  // zero pad k=201..203
        }
        feat_s[(k >> 2) * 256 + swz(p) * 4 + (k & 3)] = v;
    }
    __syncthreads();

    // ---- Phase 3: GEMM + epilogue ----
    // tid = uvc*16 + pt ; uvc -> (c-in-chunk, u, v), pt -> 4-pixel group
    const int uvc = tid >> 4;            // 0..15
    const int pt  = tid & 15;            // 0..15
    const int cl  = uvc >> 2;            // 0..3
    const int uv  = uvc & 3;
    const int u   = uv >> 1, vv = uv & 1;

    int fchunk[4];
    #pragma unroll
    for (int pp = 0; pp < 4; ++pp) fchunk[pp] = swz(pt * 4 + pp);
    const ulonglong2* fsb = (const ulonglong2*)feat_s;

    for (int c4 = 0; c4 < 8; ++c4) {
        const int c = c4 * 4 + cl;
        const float* wb = g_wpack + (size_t)(c * 36 + uv) * KP;

        unsigned long long acc[9][4];
        #pragma unroll
        for (int kk = 0; kk < 9; ++kk)
            #pragma unroll
            for (int pp = 0; pp < 4; ++pp) acc[kk][pp] = 0ull;

        for (int kq = 0; kq < NKQ; ++kq) {
            ulonglong2 f[4];
            #pragma unroll
            for (int pp = 0; pp < 4; ++pp) f[pp] = fsb[kq * 64 + fchunk[pp]];
            #pragma unroll
            for (int kk = 0; kk < 9; ++kk) {
                ulonglong2 wvv = *(const ulonglong2*)(wb + kk * (4 * KP) + kq * 4);
                #pragma unroll
                for (int pp = 0; pp < 4; ++pp) {
                    fma2(acc[kk][pp], wvv.x, f[pp].x);
                    fma2(acc[kk][pp], wvv.y, f[pp].y);
                }
            }
        }

        // Epilogue: y = relu(sum + bias); out = mean_kk(patch * y)
        float bia[9];
        #pragma unroll
        for (int kk = 0; kk < 9; ++kk) bia[kk] = g_bias[c * 36 + kk * 4 + uv];

        #pragma unroll
        for (int pp = 0; pp < 4; ++pp) {
            int p = pt * 4 + pp;
            float o = 0.f;
            #pragma unroll
            for (int kk = 0; kk < 9; ++kk) {
                float2 t = u2f(acc[kk][pp]);
                float y = fmaxf(t.x + t.y + bia[kk], 0.f);
                o += patch_s[(c * KK_ + kk) * PTILE + p] * y;
            }
            o *= (1.f / 9.f);
            int oyl = p >> 3, oxl = p & 7;
            out[(((size_t)b * C_ + c) * 128 + 2 * (oy0 + oyl) + u) * 128
                + 2 * (ox0 + oxl) + vv] = o;
        }
    }
}

// ---------------------------------------------------------------------------
extern "C" void kernel_launch(void* const* d_in, const int* in_sizes, int n_in,
                              void* d_out, int out_size) {
    const float* x     = (const float*)d_in[0];
    const float* cw    = (const float*)d_in[1];
    const float* gam   = (const float*)d_in[2];
    const float* bet   = (const float*)d_in[3];
    const float* mn    = (const float*)d_in[4];
    const float* vr    = (const float*)d_in[5];
    float* out         = (float*)d_out;

    cudaFuncSetAttribute(revo_main, cudaFuncAttributeMaxDynamicSharedMemorySize,
                         SMEM_BYTES);

    repack_kernel<<<OUTCH, 128>>>(cw, gam, bet, mn, vr);
    dim3 grid(OW_ / 8, OH_ / 8, B_);
    revo_main<<<grid, 256, SMEM_BYTES>>>(x, out);
}

// round 3
// speedup vs baseline: 5.5517x; 5.5517x over previous
#include <cuda_runtime.h>
#include <cuda_fp16.h>
#include <math.h>
#include <cstdint>

// ---------------------------------------------------------------------------
// Problem constants
// ---------------------------------------------------------------------------
#define C_      32
#define B_      8
#define INCH    201          // K*C*2 + K*K
#define KH      208          // K padded to 13 x 16 (halves)
#define KST     13           // k16 steps
#define NCH     72           // N per chunk (exactly 2 channels x 36)
#define NCHUNKS 16           // 1152 / 72
#define FSTR_H  216          // feat/B row stride in halves (27 x 16B, coprime 8)
#define FSTR_B  432          // ... in bytes

// SMEM layout (bytes)
#define XS_FL    (32*33*17)                 // 17952 floats
#define XS_OFF   0
#define BIAS_OFF (XS_FL*4)                  // 71808
#define FEAT_OFF (BIAS_OFF + 1152*4)        // 76416
#define B0_OFF   (FEAT_OFF + 128*FSTR_B)    // 131712
#define BBYTES   (NCH*FSTR_B)               // 31104
#define B1_OFF   (B0_OFF + BBYTES)          // 162816
#define YB_OFF   (B1_OFF + BBYTES)          // 193920
#define YSTR     74
#define SMEM_BYTES (YB_OFF + 128*YSTR*4)    // 231808 (< 232448 max)

// ---------------------------------------------------------------------------
// Static scratch (no allocations)
// ---------------------------------------------------------------------------
__device__ __half g_wh[1152 * KH];   // BN-folded fp16 weights, K-padded
__device__ float  g_bias[1152];

// ---------------------------------------------------------------------------
// PTX helpers (sm_103 BASE features only: ldmatrix / mma.sync / cp.async)
// ---------------------------------------------------------------------------
__device__ __forceinline__ uint32_t su32(const void* p) {
    uint32_t a;
    asm("{ .reg .u64 t; cvta.to.shared.u64 t, %1; cvt.u32.u64 %0, t; }" : "=r"(a) : "l"(p));
    return a;
}
__device__ __forceinline__ void ldsm4(uint32_t* r, uint32_t a) {
    asm volatile("ldmatrix.sync.aligned.m8n8.x4.shared.b16 {%0,%1,%2,%3}, [%4];"
                 : "=r"(r[0]), "=r"(r[1]), "=r"(r[2]), "=r"(r[3]) : "r"(a));
}
__device__ __forceinline__ void ldsm2(uint32_t* r, uint32_t a) {
    asm volatile("ldmatrix.sync.aligned.m8n8.x2.shared.b16 {%0,%1}, [%2];"
                 : "=r"(r[0]), "=r"(r[1]) : "r"(a));
}
__device__ __forceinline__ void mma16816(float* c, const uint32_t* a, const uint32_t* b) {
    asm volatile("mma.sync.aligned.m16n8k16.row.col.f32.f16.f16.f32 "
                 "{%0,%1,%2,%3}, {%4,%5,%6,%7}, {%8,%9}, {%0,%1,%2,%3};"
                 : "+f"(c[0]), "+f"(c[1]), "+f"(c[2]), "+f"(c[3])
                 : "r"(a[0]), "r"(a[1]), "r"(a[2]), "r"(a[3]), "r"(b[0]), "r"(b[1]));
}
__device__ __forceinline__ void cpasync16(uint32_t dst, const void* src) {
    asm volatile("cp.async.cg.shared.global [%0], [%1], 16;" :: "r"(dst), "l"(src));
}
__device__ __forceinline__ void cpcommit() { asm volatile("cp.async.commit_group;"); }
__device__ __forceinline__ void cpwait0()  { asm volatile("cp.async.wait_group 0;" ::: "memory"); }

// ---------------------------------------------------------------------------
// Repack: fold BN into conv_w, convert fp16, pad K 201->208
// ---------------------------------------------------------------------------
__global__ void repack_kernel(const float* __restrict__ w,
                              const float* __restrict__ gamma,
                              const float* __restrict__ beta,
                              const float* __restrict__ mean,
                              const float* __restrict__ var) {
    int m = blockIdx.x;
    float sc = gamma[m] * rsqrtf(var[m] + 1e-5f);
    if (threadIdx.x == 0) g_bias[m] = beta[m] - mean[m] * sc;
    for (int k = threadIdx.x; k < KH; k += blockDim.x) {
        float v = (k < INCH) ? w[m * INCH + k] * sc : 0.f;
        g_wh[m * KH + k] = __float2half_rn(v);
    }
}

// Stage one 72-row N-chunk of fp16 weights into SMEM [n][k], stride 216 halves
__device__ __forceinline__ void stage_b(uint32_t bufs, int n0, int tid) {
    for (int e = tid; e < NCH * 26; e += 256) {
        int r = e / 26, q = e - r * 26;
        cpasync16(bufs + r * FSTR_B + q * 16,
                  g_wh + (size_t)(n0 + r) * KH + q * 8);
    }
}

// ---------------------------------------------------------------------------
// One N-chunk GEMM: 128(M) x (NT*8)(N) x 208(K), warp covers M=32, NT n-tiles.
// acc layout [nt][mt][4] (mma C frags). bbase points at this warp's n-tile 0.
// ---------------------------------------------------------------------------
template <int NT>
__device__ __forceinline__ void gemm_chunk(uint32_t fbase, uint32_t bbase,
                                           int m0, int lane, float acc[][2][4]) {
    #pragma unroll
    for (int s = 0; s < KST; ++s) {
        uint32_t a[2][4];
        #pragma unroll
        for (int mt = 0; mt < 2; ++mt) {
            uint32_t ad = fbase + (uint32_t)(m0 + mt * 16 + (lane & 15)) * FSTR_B
                        + s * 32 + (lane >> 4) * 16;
            ldsm4(a[mt], ad);
        }
        uint32_t bf[NT][2];
        #pragma unroll
        for (int pq = 0; pq < NT / 2; ++pq) {
            uint32_t ad = bbase
                        + (uint32_t)((pq * 2 + (lane >> 4)) * 8 + (lane & 7)) * FSTR_B
                        + s * 32 + ((lane >> 3) & 1) * 16;
            uint32_t t4[4];
            ldsm4(t4, ad);
            bf[2 * pq][0] = t4[0]; bf[2 * pq][1] = t4[1];
            bf[2 * pq + 1][0] = t4[2]; bf[2 * pq + 1][1] = t4[3];
        }
        if (NT & 1) {
            uint32_t ad = bbase + (uint32_t)((NT - 1) * 8 + (lane & 7)) * FSTR_B
                        + s * 32 + ((lane >> 3) & 1) * 16;
            ldsm2(bf[NT - 1], ad);
        }
        #pragma unroll
        for (int nt = 0; nt < NT; ++nt)
            #pragma unroll
            for (int mt = 0; mt < 2; ++mt)
                mma16816(acc[nt][mt], a[mt], bf[nt]);
    }
}

// ---------------------------------------------------------------------------
// Main fused kernel: CTA = 128 pixels (16 oy x 8 ox) of one batch image
// ---------------------------------------------------------------------------
__global__ __launch_bounds__(256, 1)
void revo_hmma(const float* __restrict__ x, float* __restrict__ out) {
    extern __shared__ char smem[];
    float*  xs     = (float*)(smem + XS_OFF);
    float*  bias_s = (float*)(smem + BIAS_OFF);
    __half* feat   = (__half*)(smem + FEAT_OFF);
    float*  ybuf   = (float*)(smem + YB_OFF);
    const uint32_t sb = su32(smem);

    const int tid = threadIdx.x, lane = tid & 31, wid = tid >> 5;
    const int b = blockIdx.z, oy0 = blockIdx.y * 16, ox0 = blockIdx.x * 8;

    // stage weight chunk 0 early (overlaps x-tile load)
    stage_b(sb + B0_OFF, 0, tid);
    cpcommit();

    // ---- x tile [32][33][17], zero-padded halo + bias ----
    const float* xb = x + (size_t)b * C_ * 16384;
    for (int e = tid; e < XS_FL; e += 256) {
        int c = e / 561, rem = e - c * 561;
        int yy = rem / 17, xx = rem - yy * 17;
        int iy = 2 * oy0 - 1 + yy, ix = 2 * ox0 - 1 + xx;
        float v = 0.f;
        if ((unsigned)iy < 128u && (unsigned)ix < 128u) v = xb[c * 16384 + iy * 128 + ix];
        xs[e] = v;
    }
    for (int e = tid; e < 1152; e += 256) bias_s[e] = g_bias[e];
    __syncthreads();

    // ---- feat build: 201 features per pixel -> fp16 A matrix [p][k] ----
    if (tid < 128) {
        const int p = tid, oyl = p >> 3, oxl = p & 7;
        const int pb = (2 * oyl) * 17 + 2 * oxl;
        __half* fr = feat + p * FSTR_H;
        float cm[9];
        #pragma unroll
        for (int kk = 0; kk < 9; ++kk) cm[kk] = -3.402823466e38f;
        for (int c = 0; c < C_; ++c) {
            const float* xc = xs + c * 561 + pb;
            float ph[9];
            #pragma unroll
            for (int ki = 0; ki < 3; ++ki)
                #pragma unroll
                for (int kj = 0; kj < 3; ++kj) ph[ki * 3 + kj] = xc[ki * 17 + kj];
            #pragma unroll
            for (int kk = 0; kk < 9; ++kk) cm[kk] = fmaxf(cm[kk], ph[kk]);
            #pragma unroll
            for (int j = 0; j < 3; ++j)   // max over kernel rows
                fr[9 + c * 3 + j] =
                    __float2half_rn(fmaxf(fmaxf(ph[j], ph[3 + j]), ph[6 + j]));
            #pragma unroll
            for (int i = 0; i < 3; ++i)   // max over kernel cols
                fr[105 + c * 3 + i] =
                    __float2half_rn(fmaxf(fmaxf(ph[3 * i], ph[3 * i + 1]), ph[3 * i + 2]));
        }
        #pragma unroll
        for (int kk = 0; kk < 9; ++kk) fr[kk] = __float2half_rn(cm[kk]);
        #pragma unroll
        for (int k = INCH; k < KH; ++k) fr[k] = __ushort_as_half(0);
    }
    cpwait0();
    __syncthreads();

    // warp tiling: 4 M-groups x 2 N-groups (5 / 4 n-tiles of the 9)
    const int m0 = (wid >> 1) * 32;
    const int ngrp = wid & 1;
    const int tb = ngrp ? 5 : 0;            // n-tile base
    const int g = lane >> 2, tg = lane & 3;

    for (int t = 0; t < NCHUNKS; ++t) {
        const uint32_t bb = sb + ((t & 1) ? B1_OFF : B0_OFF);
        if (t + 1 < NCHUNKS) {              // prefetch next weight chunk
            stage_b(sb + (((t + 1) & 1) ? B1_OFF : B0_OFF), (t + 1) * NCH, tid);
        }
        cpcommit();

        float acc[5][2][4];
        #pragma unroll
        for (int i = 0; i < 5; ++i)
            #pragma unroll
            for (int j = 0; j < 2; ++j)
                #pragma unroll
                for (int k = 0; k < 4; ++k) acc[i][j][k] = 0.f;

        if (ngrp == 0) gemm_chunk<5>(sb + FEAT_OFF, bb, m0, lane, acc);
        else           gemm_chunk<4>(sb + FEAT_OFF, bb + 5 * 8 * FSTR_B, m0, lane, acc);

        // C frags -> ybuf[p][n]
        const int NTloc = ngrp ? 4 : 5;
        #pragma unroll
        for (int nt = 0; nt < 5; ++nt) {
            if (nt < NTloc) {
                #pragma unroll
                for (int mt = 0; mt < 2; ++mt) {
                    int p0 = m0 + mt * 16 + g;
                    int n = (tb + nt) * 8 + 2 * tg;
                    *(float2*)(ybuf + p0 * YSTR + n) =
                        make_float2(acc[nt][mt][0], acc[nt][mt][1]);
                    *(float2*)(ybuf + (p0 + 8) * YSTR + n) =
                        make_float2(acc[nt][mt][2], acc[nt][mt][3]);
                }
            }
        }
        __syncthreads();

        // fused epilogue: thread = (pixel, channel-of-chunk)
        {
            const int p = tid >> 1, dc = tid & 1;
            const int oyl = p >> 3, oxl = p & 7;
            const int c = t * 2 + dc;
            const float* xc = xs + c * 561 + (2 * oyl) * 17 + 2 * oxl;
            float ph[9];
            #pragma unroll
            for (int ki = 0; ki < 3; ++ki)
                #pragma unroll
                for (int kj = 0; kj < 3; ++kj) ph[ki * 3 + kj] = xc[ki * 17 + kj];
            const float* yb = ybuf + p * YSTR + dc * 36;
            const float* bs = bias_s + t * NCH + dc * 36;
            float o[4] = {0.f, 0.f, 0.f, 0.f};
            #pragma unroll
            for (int kk = 0; kk < 9; ++kk) {
                const float pv = ph[kk];
                #pragma unroll
                for (int uv = 0; uv < 4; ++uv)
                    o[uv] += pv * fmaxf(yb[kk * 4 + uv] + bs[kk * 4 + uv], 0.f);
            }
            const float inv9 = 1.f / 9.f;
            const size_t ob = ((size_t)(b * C_ + c) * 128 + 2 * (oy0 + oyl)) * 128
                            + 2 * (ox0 + oxl);
            *(float2*)(out + ob)       = make_float2(o[0] * inv9, o[1] * inv9);
            *(float2*)(out + ob + 128) = make_float2(o[2] * inv9, o[3] * inv9);
        }
        cpwait0();
        __syncthreads();
    }
}

// ---------------------------------------------------------------------------
extern "C" void kernel_launch(void* const* d_in, const int* in_sizes, int n_in,
                              void* d_out, int out_size) {
    const float* x   = (const float*)d_in[0];
    const float* cw  = (const float*)d_in[1];
    const float* gam = (const float*)d_in[2];
    const float* bet = (const float*)d_in[3];
    const float* mn  = (const float*)d_in[4];
    const float* vr  = (const float*)d_in[5];
    float* out       = (float*)d_out;

    cudaFuncSetAttribute(revo_hmma, cudaFuncAttributeMaxDynamicSharedMemorySize,
                         SMEM_BYTES);

    repack_kernel<<<1152, 128>>>(cw, gam, bet, mn, vr);
    dim3 grid(8, 4, B_);
    revo_hmma<<<grid, 256, SMEM_BYTES>>>(x, out);
}